// round 16
// baseline (speedup 1.0000x reference)
#include <cuda_runtime.h>
#include <cstdint>
#include <math.h>

// ---------------- problem constants ----------------
#define BB   512
#define SS   128
#define EE   640
#define AA   129
#define HH   2048
#define NH   10
#define HD   64
#define KWIN 64
#define BS   (BB*SS)          // 65536
#define KFLAT (EE*SS)         // 81920
#define LDW1 (KFLAT + AA)     // 82049
#define FC1_SPLITS 32
#define FC1_KLOC   (KFLAT/FC1_SPLITS)   // 2560

// ---------------- scratch (device globals, no allocs) ----------------
__device__ float g_h[BS * EE];          // h; later fc1 split-K partials
__device__ float g_qkv[BS * 3 * EE];    // qkv; later fc2/3/4 partials
__device__ float g_ctx[BS * EE];        // ctx; x_flat
__device__ float g_ao[BS * EE];         // attn_out (+h fused)
__device__ float g_t1[BB * HH];
__device__ float g_t2[BB * HH];
__device__ float g_t3[BB * (HH/2)];
__device__ float g_t4[BB * (HH/4)];
__device__ float g_t5[BB * AA];

// ================= helpers =================
#define MMA_BF16(c, a, b) \
    asm volatile("mma.sync.aligned.m16n8k16.row.col.f32.bf16.bf16.f32 " \
        "{%0,%1,%2,%3}, {%4,%5,%6,%7}, {%8,%9}, {%0,%1,%2,%3};" \
        : "+f"((c)[0]), "+f"((c)[1]), "+f"((c)[2]), "+f"((c)[3]) \
        : "r"((a)[0]), "r"((a)[1]), "r"((a)[2]), "r"((a)[3]), \
          "r"((b)[0]), "r"((b)[1]))
#define LDSM4(r0, r1, r2, r3, addr) \
    asm volatile("ldmatrix.sync.aligned.m8n8.x4.shared.b16 {%0,%1,%2,%3}, [%4];" \
        : "=r"(r0), "=r"(r1), "=r"(r2), "=r"(r3) : "r"(addr))

__device__ __forceinline__ uint32_t smem_u32(const void* p) {
    uint32_t a;
    asm("{ .reg .u64 t; cvta.to.shared.u64 t, %1; cvt.u32.u64 %0, t; }" : "=r"(a) : "l"(p));
    return a;
}
// L1-bypass vector/scalar global loads (L2-only)
__device__ __forceinline__ float4 ldg_cg4(const float* p) {
    float4 v;
    asm volatile("ld.global.cg.v4.f32 {%0,%1,%2,%3}, [%4];"
        : "=f"(v.x), "=f"(v.y), "=f"(v.z), "=f"(v.w) : "l"(p));
    return v;
}
__device__ __forceinline__ float ldg_cg1(const float* p) {
    float v;
    asm volatile("ld.global.cg.f32 %0, [%1];" : "=f"(v) : "l"(p));
    return v;
}

// split fp32x4 -> bf16x2 (hi,lo) pairs and store to smem (2 u32 words each)
__device__ __forceinline__ void splitStoreBf(float4 f, uint32_t* hi, uint32_t* lo, int off) {
    uint32_t h01, h23;
    asm("cvt.rn.bf16x2.f32 %0, %1, %2;" : "=r"(h01) : "f"(f.y), "f"(f.x));
    asm("cvt.rn.bf16x2.f32 %0, %1, %2;" : "=r"(h23) : "f"(f.w), "f"(f.z));
    float hx = __uint_as_float(h01 << 16);
    float hy = __uint_as_float(h01 & 0xFFFF0000u);
    float hz = __uint_as_float(h23 << 16);
    float hw = __uint_as_float(h23 & 0xFFFF0000u);
    uint32_t l01, l23;
    asm("cvt.rn.bf16x2.f32 %0, %1, %2;" : "=r"(l01) : "f"(f.y - hy), "f"(f.x - hx));
    asm("cvt.rn.bf16x2.f32 %0, %1, %2;" : "=r"(l23) : "f"(f.w - hw), "f"(f.z - hz));
    hi[off] = h01; hi[off + 1] = h23;
    lo[off] = l01; lo[off + 1] = l23;
}
// split two scalars into one bf16x2 hi word + lo word
__device__ __forceinline__ void splitPairBf(float v0, float v1, uint32_t& hp, uint32_t& lp) {
    asm("cvt.rn.bf16x2.f32 %0, %1, %2;" : "=r"(hp) : "f"(v1), "f"(v0));
    float h0 = __uint_as_float(hp << 16);
    float h1 = __uint_as_float(hp & 0xFFFF0000u);
    asm("cvt.rn.bf16x2.f32 %0, %1, %2;" : "=r"(lp) : "f"(v1 - h1), "f"(v0 - h0));
}

// ============== 3xBF16 mma.sync GEMM:  C = A(M,K) @ W(N,K)^T ==============
// EPI: 0 bias | 3 raw partial (split-K) | 4 bias + Res add (no relu).
// Block tile 128x128, BK=32, 256 threads, warp grid 2x4, warp tile 64x32.
// Fragment loads via ldmatrix.x4; gmem operand loads bypass L1 (.cg).
#define RS32 20
#define A_U32 (128*RS32)
#define W_U32 (128*RS32)
#define BUF_U32 (2*A_U32 + 2*W_U32)
#define TG_SMEM (2*BUF_U32*4)             // 81920 B
template<int EPI>
__global__ void __launch_bounds__(256, 2)
tgemm_bf16(const float* __restrict__ A, long lda,
           const float* __restrict__ W, long ldw,
           const float* __restrict__ bias, const float* __restrict__ Res,
           float* __restrict__ C, long ldc, int Kloc, long partStride)
{
    extern __shared__ uint32_t smu[];

    const int tid = threadIdx.x;
    const int wid = tid >> 5;
    const int lane = tid & 31;
    const int g   = lane >> 2;
    const int tig = lane & 3;
    const int wm = (wid & 1) * 64;
    const int wn = (wid >> 1) * 32;

    const int m0 = blockIdx.y * 128;
    const int n0 = blockIdx.x * 128;
    const long kbase = (long)blockIdx.z * Kloc;
    float* Cp = C + (EPI == 3 ? (long)blockIdx.z * partStride : 0);
    const bool wal = ((ldw & 3) == 0);
    const int KT = Kloc / 32;

    const uint32_t sbase = smem_u32(smu);
    // ldmatrix per-lane offsets (u32 units)
    const int aoff = (lane & 15) * RS32 + (lane >> 4) * 4;               // A x4
    const int sub  = lane >> 3;
    const int boff = ((lane & 7) + (sub >> 1) * 8) * RS32 + (sub & 1) * 4; // B x4 (2 nt)

    float acc[4][4][4];
#pragma unroll
    for (int mt = 0; mt < 4; mt++)
#pragma unroll
        for (int nt = 0; nt < 4; nt++)
#pragma unroll
            for (int r = 0; r < 4; r++) acc[mt][nt][r] = 0.f;

    float4 fa[4], fw[4];

    auto loadFrag = [&](int kt) {
        const long kk = kbase + (long)kt * 32;
#pragma unroll
        for (int i = 0; i < 4; i++) {
            int c = tid + i * 256; int row = c >> 3, q = c & 7;
            fa[i] = ldg_cg4(A + (size_t)(m0 + row) * lda + kk + q * 4);
            const float* pw = W + (size_t)(n0 + row) * ldw + kk + q * 4;
            if (wal) fw[i] = ldg_cg4(pw);
            else     fw[i] = make_float4(ldg_cg1(pw), ldg_cg1(pw+1), ldg_cg1(pw+2), ldg_cg1(pw+3));
        }
    };
    auto storeFrag = [&](int sbi) {
        uint32_t* Ah = smu + sbi * BUF_U32;
        uint32_t* Al = Ah + A_U32;
        uint32_t* Wh = Al + A_U32;
        uint32_t* Wl = Wh + W_U32;
#pragma unroll
        for (int i = 0; i < 4; i++) {
            int c = tid + i * 256; int row = c >> 3, q = c & 7;
            splitStoreBf(fa[i], Ah, Al, row * RS32 + q * 2);
            splitStoreBf(fw[i], Wh, Wl, row * RS32 + q * 2);
        }
    };
    auto compute = [&](int sbi) {
        const uint32_t bA  = sbase + (sbi * BUF_U32) * 4;
        const uint32_t bAl = bA + A_U32 * 4;
        const uint32_t bW  = bAl + A_U32 * 4;
        const uint32_t bWl = bW + W_U32 * 4;
#pragma unroll
        for (int ks = 0; ks < 2; ks++) {
            const int kw = ks * 8;
            uint32_t bh[4][2], bl[4][2];
#pragma unroll
            for (int p = 0; p < 2; p++) {
                const uint32_t off = ((wn + p * 16) * RS32 + kw + boff) * 4;
                LDSM4(bh[2*p][0], bh[2*p][1], bh[2*p+1][0], bh[2*p+1][1], bW  + off);
                LDSM4(bl[2*p][0], bl[2*p][1], bl[2*p+1][0], bl[2*p+1][1], bWl + off);
            }
#pragma unroll
            for (int mt = 0; mt < 4; mt++) {
                const uint32_t off = ((wm + mt * 16) * RS32 + kw + aoff) * 4;
                uint32_t ah[4], al[4];
                LDSM4(ah[0], ah[1], ah[2], ah[3], bA  + off);
                LDSM4(al[0], al[1], al[2], al[3], bAl + off);
#pragma unroll
                for (int nt = 0; nt < 4; nt++) {
                    MMA_BF16(acc[mt][nt], al, bh[nt]);
                    MMA_BF16(acc[mt][nt], ah, bl[nt]);
                    MMA_BF16(acc[mt][nt], ah, bh[nt]);
                }
            }
        }
    };

    loadFrag(0);
    storeFrag(0);
    if (KT > 1) loadFrag(1);
    __syncthreads();

    for (int kt = 0; kt < KT; kt++) {
        if (kt + 1 < KT) storeFrag((kt + 1) & 1);
        if (kt + 2 < KT) loadFrag(kt + 2);
        compute(kt & 1);
        __syncthreads();
    }

#pragma unroll
    for (int mt = 0; mt < 4; mt++) {
#pragma unroll
        for (int nt = 0; nt < 4; nt++) {
            const int col = n0 + wn + nt * 8 + 2 * tig;
            float2 b2 = make_float2(0.f, 0.f);
            if (EPI != 3) b2 = *reinterpret_cast<const float2*>(bias + col);
#pragma unroll
            for (int half = 0; half < 2; half++) {
                const int row = m0 + wm + mt * 16 + g + half * 8;
                float vx = acc[mt][nt][2*half + 0] + b2.x;
                float vy = acc[mt][nt][2*half + 1] + b2.y;
                if (EPI == 4) {
                    float2 r2 = *reinterpret_cast<const float2*>(Res + (size_t)row * ldc + col);
                    vx += r2.x; vy += r2.y;
                }
                *reinterpret_cast<float2*>(Cp + (size_t)row * ldc + col) = make_float2(vx, vy);
            }
        }
    }
}

// ============== generic split-K reduce: bias [+relu] [+res] ==============
template<int NSPLIT, int EPI>
__global__ void red_epi(const float* __restrict__ part, long stride,
                        const float* __restrict__ bias, const float* __restrict__ Res,
                        float* __restrict__ out, int N)
{
    const int m = blockIdx.y;
    const int n = blockIdx.x * 256 + threadIdx.x;
    float s = bias[n];
#pragma unroll
    for (int z = 0; z < NSPLIT; z++)
        s += part[(size_t)z * stride + (size_t)m * N + n];
    s = fmaxf(s, 0.f);
    if (EPI == 2) s += Res[(size_t)m * N + n];
    out[(size_t)m * N + n] = s;
}

// ============== fc1 split-K reduce + bias + last_action tail + relu ==============
__global__ void red_fc1(const float* __restrict__ part, const float* __restrict__ la,
                        const float* __restrict__ w1, const float* __restrict__ b1,
                        float* __restrict__ t1)
{
    const int m = blockIdx.y;
    const int n = blockIdx.x * 256 + threadIdx.x;
    __shared__ float las[AA];
    if (threadIdx.x < AA) las[threadIdx.x] = la[m * AA + threadIdx.x];
    __syncthreads();
    float s = b1[n];
#pragma unroll
    for (int z = 0; z < FC1_SPLITS; z++)
        s += part[(size_t)z * (BB * HH) + (size_t)m * HH + n];
    const float* w = w1 + (size_t)n * LDW1 + KFLAT;
    float acc = 0.f;
    for (int j = 0; j < AA; j++) acc += las[j] * w[j];
    t1[(size_t)m * HH + n] = fmaxf(s + acc, 0.f);
}

// ================= fp32 fallback GEMM (fc5 only, N=129 ragged) =================
template<int BM, int BN, int BK, int TM, int TN>
__global__ void __launch_bounds__((BM/TM)*(BN/TN))
gemm_tn(const float* __restrict__ A, int lda,
        const float* __restrict__ W, int ldw,
        const float* __restrict__ bias,
        float* __restrict__ C, int M, int N, int K)
{
    constexpr int THREADS = (BM/TM)*(BN/TN);
    constexpr int KV = BK / 4;
    __shared__ __align__(16) float As[BK][BM];
    __shared__ __align__(16) float Ws[BK][BN];
    const int tid = threadIdx.x;
    const int m0 = blockIdx.y * BM;
    const int n0 = blockIdx.x * BN;
    const int tnx = tid % (BN/TN);
    const int tmy = tid / (BN/TN);
    float acc[TM][TN];
#pragma unroll
    for (int i = 0; i < TM; i++)
#pragma unroll
        for (int j = 0; j < TN; j++) acc[i][j] = 0.f;
    for (int k0 = 0; k0 < K; k0 += BK) {
#pragma unroll
        for (int it = 0; it < (BM*KV)/THREADS; it++) {
            int v = tid + it * THREADS; int row = v / KV, kq = v % KV;
            float4 f = make_float4(0.f,0.f,0.f,0.f);
            if (m0 + row < M) f = *reinterpret_cast<const float4*>(A + (size_t)(m0+row)*lda + k0 + kq*4);
            As[kq*4+0][row]=f.x; As[kq*4+1][row]=f.y; As[kq*4+2][row]=f.z; As[kq*4+3][row]=f.w;
        }
#pragma unroll
        for (int it = 0; it < (BN*KV)/THREADS; it++) {
            int v = tid + it * THREADS; int row = v / KV, kq = v % KV;
            float4 f = make_float4(0.f,0.f,0.f,0.f);
            if (n0 + row < N) f = *reinterpret_cast<const float4*>(W + (size_t)(n0+row)*ldw + k0 + kq*4);
            Ws[kq*4+0][row]=f.x; Ws[kq*4+1][row]=f.y; Ws[kq*4+2][row]=f.z; Ws[kq*4+3][row]=f.w;
        }
        __syncthreads();
#pragma unroll
        for (int kk = 0; kk < BK; kk++) {
            float a[TM], w[TN];
#pragma unroll
            for (int i = 0; i < TM; i++) a[i] = As[kk][tmy*TM + i];
#pragma unroll
            for (int j = 0; j < TN; j++) w[j] = Ws[kk][tnx*TN + j];
#pragma unroll
            for (int i = 0; i < TM; i++)
#pragma unroll
                for (int j = 0; j < TN; j++) acc[i][j] += a[i] * w[j];
        }
        __syncthreads();
    }
#pragma unroll
    for (int i = 0; i < TM; i++) {
        int m = m0 + tmy*TM + i; if (m >= M) continue;
#pragma unroll
        for (int j = 0; j < TN; j++) {
            int n = n0 + tnx*TN + j; if (n >= N) continue;
            C[(size_t)m * N + n] = acc[i][j] + bias[n];
        }
    }
}

// ================= attention via 3xBF16 MMA, register softmax, 2 CTAs/SM =================
#define ATT_RS  36
#define ATT_PRS 68
#define ATT_VRS 68
#define ATT_SMEM (28160*4)    // 112640 B
__global__ void __launch_bounds__(256, 2)
attn_mma_kernel(const float* __restrict__ qkv, float* __restrict__ ctx)
{
    extern __shared__ uint32_t su[];
    uint32_t* Qh = su;
    uint32_t* Ql = su + 4608;
    uint32_t* Kh = su + 9216;
    uint32_t* Kl = su + 13824;
    float*    Vst = reinterpret_cast<float*>(su + 18432);   // [128][68]
    uint32_t* Vth = su;                                      // after S-MMA
    uint32_t* Vtl = su + 4352;
    uint32_t* Ph  = su + 9216;                               // [128][68]
    uint32_t* Pl  = su + 17920;
    float*    scrM = reinterpret_cast<float*>(su + 27136);   // [128][4]
    float*    scrS = reinterpret_cast<float*>(su + 27648);   // [128][4]

    const int b = blockIdx.x / NH;
    const int h = blockIdx.x % NH;
    const int tid = threadIdx.x;
    const int wid = tid >> 5;
    const int lane = tid & 31;
    const int g   = lane >> 2;
    const int tig = lane & 3;
    const int wm  = (wid & 1) * 64;
    const int wn  = (wid >> 1) * 32;
    const int wnIdx = wid >> 1;
    const size_t base = (size_t)b * SS * (3*EE) + (size_t)h * HD;

    // phase 1: Q (scaled) & K -> hi/lo planes; V -> fp32 staging
#pragma unroll
    for (int i = 0; i < 8; i++) {
        int c = tid + i * 256;
        int row = c >> 4, q4 = c & 15;
        const float* p = qkv + base + (size_t)row * (3*EE);
        float4 fq = *reinterpret_cast<const float4*>(p + q4*4);
        fq.x *= 0.125f; fq.y *= 0.125f; fq.z *= 0.125f; fq.w *= 0.125f;
        splitStoreBf(fq, Qh, Ql, row*ATT_RS + q4*2);
        float4 fk = *reinterpret_cast<const float4*>(p + EE + q4*4);
        splitStoreBf(fk, Kh, Kl, row*ATT_RS + q4*2);
        float4 fv = *reinterpret_cast<const float4*>(p + 2*EE + q4*4);
        *reinterpret_cast<float4*>(Vst + row*68 + q4*4) = fv;
    }
    __syncthreads();

    // phase 2: S = Q @ K^T, accs stay in registers
    float acc[4][4][4];
#pragma unroll
    for (int mt = 0; mt < 4; mt++)
#pragma unroll
        for (int nt = 0; nt < 4; nt++)
#pragma unroll
            for (int r = 0; r < 4; r++) acc[mt][nt][r] = 0.f;

#pragma unroll
    for (int c = 0; c < 4; c++) {
        const int kb = c * 8;
        uint32_t bh[4][2], bl[4][2];
#pragma unroll
        for (int nt = 0; nt < 4; nt++) {
            const int r = (wn + nt*8 + g)*ATT_RS + kb + tig;
            bh[nt][0] = Kh[r]; bh[nt][1] = Kh[r + 4];
            bl[nt][0] = Kl[r]; bl[nt][1] = Kl[r + 4];
        }
#pragma unroll
        for (int mt = 0; mt < 4; mt++) {
            const int r = (wm + mt*16 + g)*ATT_RS + kb + tig;
            uint32_t ah[4], al[4];
            ah[0] = Qh[r]; ah[1] = Qh[r + 8*ATT_RS];
            ah[2] = Qh[r + 4]; ah[3] = Qh[r + 8*ATT_RS + 4];
            al[0] = Ql[r]; al[1] = Ql[r + 8*ATT_RS];
            al[2] = Ql[r + 4]; al[3] = Ql[r + 8*ATT_RS + 4];
#pragma unroll
            for (int nt = 0; nt < 4; nt++) {
                MMA_BF16(acc[mt][nt], al, bh[nt]);
                MMA_BF16(acc[mt][nt], ah, bl[nt]);
                MMA_BF16(acc[mt][nt], ah, bh[nt]);
            }
        }
    }
    __syncthreads();   // Q/K reads done; safe to overwrite Q area

    // phase 3: transpose V -> planes (Q area)  +  write per-warp row maxes
#pragma unroll
    for (int i = 0; i < 16; i++) {
        int o = tid + i * 256;
        int d = o >> 6, kc = o & 63;
        float v0 = Vst[(2*kc    )*68 + d];
        float v1 = Vst[(2*kc + 1)*68 + d];
        uint32_t hp, lp;
        splitPairBf(v0, v1, hp, lp);
        Vth[d*ATT_VRS + kc] = hp;
        Vtl[d*ATT_VRS + kc] = lp;
    }
#pragma unroll
    for (int mt = 0; mt < 4; mt++)
#pragma unroll
        for (int half = 0; half < 2; half++) {
            float m = -1e30f;
#pragma unroll
            for (int nt = 0; nt < 4; nt++) {
                m = fmaxf(m, acc[mt][nt][2*half]);
                m = fmaxf(m, acc[mt][nt][2*half + 1]);
            }
            m = fmaxf(m, __shfl_xor_sync(0xffffffffu, m, 1));
            m = fmaxf(m, __shfl_xor_sync(0xffffffffu, m, 2));
            if (tig == 0) scrM[(wm + mt*16 + g + half*8)*4 + wnIdx] = m;
        }
    __syncthreads();

    // phase 4a: exp + per-warp sums
#pragma unroll
    for (int mt = 0; mt < 4; mt++)
#pragma unroll
        for (int half = 0; half < 2; half++) {
            const int row = wm + mt*16 + g + half*8;
            float mx = fmaxf(fmaxf(scrM[row*4], scrM[row*4+1]),
                             fmaxf(scrM[row*4+2], scrM[row*4+3]));
            float s = 0.f;
#pragma unroll
            for (int nt = 0; nt < 4; nt++) {
                float e0 = expf(acc[mt][nt][2*half]     - mx);
                float e1 = expf(acc[mt][nt][2*half + 1] - mx);
                acc[mt][nt][2*half]     = e0;
                acc[mt][nt][2*half + 1] = e1;
                s += e0 + e1;
            }
            s += __shfl_xor_sync(0xffffffffu, s, 1);
            s += __shfl_xor_sync(0xffffffffu, s, 2);
            if (tig == 0) scrS[row*4 + wnIdx] = s;
        }
    __syncthreads();

    // phase 4b: normalize + write P planes (K + Vst area, both dead)
#pragma unroll
    for (int mt = 0; mt < 4; mt++)
#pragma unroll
        for (int half = 0; half < 2; half++) {
            const int row = wm + mt*16 + g + half*8;
            float tot = scrS[row*4] + scrS[row*4+1] + scrS[row*4+2] + scrS[row*4+3];
            float inv = 1.f / tot;
#pragma unroll
            for (int nt = 0; nt < 4; nt++) {
                float p0 = acc[mt][nt][2*half]     * inv;
                float p1 = acc[mt][nt][2*half + 1] * inv;
                uint32_t hp, lp;
                splitPairBf(p0, p1, hp, lp);
                const int cw = (wn >> 1) + nt*4 + tig;
                Ph[row*ATT_PRS + cw] = hp;
                Pl[row*ATT_PRS + cw] = lp;
            }
        }
    __syncthreads();

    // phase 5: ctx = P @ V  (128x64x128), warp tile 64x16
    {
        const int wn2 = (wid >> 1) * 16;
        float acc2[4][2][4];
#pragma unroll
        for (int mt = 0; mt < 4; mt++)
#pragma unroll
            for (int nt = 0; nt < 2; nt++)
#pragma unroll
                for (int r = 0; r < 4; r++) acc2[mt][nt][r] = 0.f;

#pragma unroll
        for (int c = 0; c < 8; c++) {
            const int kb = c * 8;
            uint32_t bh[2][2], bl[2][2];
#pragma unroll
            for (int nt = 0; nt < 2; nt++) {
                const int r = (wn2 + nt*8 + g)*ATT_VRS + kb + tig;
                bh[nt][0] = Vth[r]; bh[nt][1] = Vth[r + 4];
                bl[nt][0] = Vtl[r]; bl[nt][1] = Vtl[r + 4];
            }
#pragma unroll
            for (int mt = 0; mt < 4; mt++) {
                const int r = (wm + mt*16 + g)*ATT_PRS + kb + tig;
                uint32_t ah[4], al[4];
                ah[0] = Ph[r]; ah[1] = Ph[r + 8*ATT_PRS];
                ah[2] = Ph[r + 4]; ah[3] = Ph[r + 8*ATT_PRS + 4];
                al[0] = Pl[r]; al[1] = Pl[r + 8*ATT_PRS];
                al[2] = Pl[r + 4]; al[3] = Pl[r + 8*ATT_PRS + 4];
#pragma unroll
                for (int nt = 0; nt < 2; nt++) {
                    MMA_BF16(acc2[mt][nt], al, bh[nt]);
                    MMA_BF16(acc2[mt][nt], ah, bl[nt]);
                    MMA_BF16(acc2[mt][nt], ah, bh[nt]);
                }
            }
        }
#pragma unroll
        for (int mt = 0; mt < 4; mt++)
#pragma unroll
            for (int nt = 0; nt < 2; nt++) {
                const int col = wn2 + nt*8 + 2*tig;
#pragma unroll
                for (int half = 0; half < 2; half++) {
                    const int row = wm + mt*16 + g + half*8;
                    *reinterpret_cast<float2*>(ctx + ((size_t)b*SS + row)*EE + h*HD + col) =
                        make_float2(acc2[mt][nt][2*half], acc2[mt][nt][2*half + 1]);
                }
            }
    }
}

// ================= layernorm: warp per row =================
template<bool ADD>
__global__ void ln_warp(const float* __restrict__ X, const float* __restrict__ Y,
                        const float* __restrict__ g, const float* __restrict__ be,
                        float* __restrict__ out, int D, int rows)
{
    const int w = (blockIdx.x * blockDim.x + threadIdx.x) >> 5;
    if (w >= rows) return;
    const int lane = threadIdx.x & 31;
    const float* x = X + (size_t)w * D;
    const float* y = ADD ? (Y + (size_t)w * D) : nullptr;
    float s = 0.f, s2 = 0.f;
    for (int c = lane * 4; c < D; c += 128) {
        float4 v = *reinterpret_cast<const float4*>(x + c);
        if (ADD) {
            float4 u = *reinterpret_cast<const float4*>(y + c);
            v.x += u.x; v.y += u.y; v.z += u.z; v.w += u.w;
        }
        s  += (v.x + v.y) + (v.z + v.w);
        s2 += (v.x*v.x + v.y*v.y) + (v.z*v.z + v.w*v.w);
    }
#pragma unroll
    for (int o = 16; o > 0; o >>= 1) {
        s  += __shfl_xor_sync(0xffffffffu, s,  o);
        s2 += __shfl_xor_sync(0xffffffffu, s2, o);
    }
    float mean = s / (float)D;
    float var  = s2 / (float)D - mean * mean;
    float inv  = rsqrtf(var + 1e-5f);
    for (int c = lane * 4; c < D; c += 128) {
        float4 v = *reinterpret_cast<const float4*>(x + c);
        if (ADD) {
            float4 u = *reinterpret_cast<const float4*>(y + c);
            v.x += u.x; v.y += u.y; v.z += u.z; v.w += u.w;
        }
        float4 gg = *reinterpret_cast<const float4*>(g + c);
        float4 bb = *reinterpret_cast<const float4*>(be + c);
        v.x = (v.x - mean) * inv * gg.x + bb.x;
        v.y = (v.y - mean) * inv * gg.y + bb.y;
        v.z = (v.z - mean) * inv * gg.z + bb.z;
        v.w = (v.w - mean) * inv * gg.w + bb.w;
        *reinterpret_cast<float4*>(out + (size_t)w * D + c) = v;
    }
}

// ================= fc6 + top-K + masked softmax =================
__global__ void head_kernel(const float* __restrict__ t5, const float* __restrict__ la,
                            const float* __restrict__ w6, const float* __restrict__ b6,
                            float* __restrict__ out)
{
    const int b = blockIdx.x;
    __shared__ float cat[2*AA];
    __shared__ float sc[AA];
    __shared__ float red[256];
    const int tid = threadIdx.x;

    for (int i = tid; i < 2*AA; i += 256)
        cat[i] = (i < AA) ? t5[b*AA + i] : la[b*AA + (i - AA)];
    __syncthreads();

    if (tid < AA) {
        float a = b6[tid];
        const float* w = w6 + tid * (2*AA);
        for (int j = 0; j < 2*AA; j++) a += w[j] * cat[j];
        sc[tid] = a;
    }
    __syncthreads();

    bool winner = false; float v = 0.f;
    if (tid < AA) {
        v = sc[tid];
        int cnt = 0;
        for (int j = 0; j < AA; j++) {
            float u = sc[j];
            cnt += (u > v) || (u == v && j < tid);
        }
        winner = cnt < KWIN;
    }
    red[tid] = (tid < AA && winner) ? v : -1e30f;
    __syncthreads();
    for (int s = 128; s > 0; s >>= 1) {
        if (tid < s) red[tid] = fmaxf(red[tid], red[tid + s]);
        __syncthreads();
    }
    float mx = red[0];
    __syncthreads();
    float e = (tid < AA && winner) ? expf(v - mx) : 0.f;
    red[tid] = e;
    __syncthreads();
    for (int s = 128; s > 0; s >>= 1) {
        if (tid < s) red[tid] += red[tid + s];
        __syncthreads();
    }
    float inv = 1.f / red[0];
    if (tid < AA) out[b*AA + tid] = e * inv;
}

// ================= launcher =================
extern "C" void kernel_launch(void* const* d_in, const int* in_sizes, int n_in,
                              void* d_out, int out_size)
{
    const float* hist      = (const float*)d_in[0];
    const float* la        = (const float*)d_in[1];
    const float* embed_w   = (const float*)d_in[2];
    const float* embed_b   = (const float*)d_in[3];
    const float* in_proj_w = (const float*)d_in[4];
    const float* in_proj_b = (const float*)d_in[5];
    const float* out_proj_w= (const float*)d_in[6];
    const float* out_proj_b= (const float*)d_in[7];
    const float* lnorm_g   = (const float*)d_in[8];
    const float* lnorm_b   = (const float*)d_in[9];
    const float* fc1_w     = (const float*)d_in[10];
    const float* fc1_b     = (const float*)d_in[11];
    const float* fc2_w     = (const float*)d_in[12];
    const float* fc2_b     = (const float*)d_in[13];
    const float* ln1_g     = (const float*)d_in[14];
    const float* ln1_b     = (const float*)d_in[15];
    const float* fc3_w     = (const float*)d_in[16];
    const float* fc3_b     = (const float*)d_in[17];
    const float* fc4_w     = (const float*)d_in[18];
    const float* fc4_b     = (const float*)d_in[19];
    const float* fc5_w     = (const float*)d_in[20];
    const float* fc5_b     = (const float*)d_in[21];
    const float* fc6_w     = (const float*)d_in[22];
    const float* fc6_b     = (const float*)d_in[23];
    float* out = (float*)d_out;

    float *h, *qkv, *ctx, *ao, *t1, *t2, *t3, *t4, *t5;
    cudaGetSymbolAddress((void**)&h,   g_h);
    cudaGetSymbolAddress((void**)&qkv, g_qkv);
    cudaGetSymbolAddress((void**)&ctx, g_ctx);
    cudaGetSymbolAddress((void**)&ao,  g_ao);
    cudaGetSymbolAddress((void**)&t1,  g_t1);
    cudaGetSymbolAddress((void**)&t2,  g_t2);
    cudaGetSymbolAddress((void**)&t3,  g_t3);
    cudaGetSymbolAddress((void**)&t4,  g_t4);
    cudaGetSymbolAddress((void**)&t5,  g_t5);

    cudaFuncSetAttribute(tgemm_bf16<0>, cudaFuncAttributeMaxDynamicSharedMemorySize, TG_SMEM);
    cudaFuncSetAttribute(tgemm_bf16<3>, cudaFuncAttributeMaxDynamicSharedMemorySize, TG_SMEM);
    cudaFuncSetAttribute(tgemm_bf16<4>, cudaFuncAttributeMaxDynamicSharedMemorySize, TG_SMEM);
    cudaFuncSetAttribute(attn_mma_kernel, cudaFuncAttributeMaxDynamicSharedMemorySize, ATT_SMEM);

    // 1) embed: h = hist @ embed_w^T + b          [65536,640]
    tgemm_bf16<0><<<dim3(EE/128, BS/128, 1), 256, TG_SMEM>>>(
        hist, EE, embed_w, EE, embed_b, nullptr, h, EE, EE, 0);

    // 2) qkv = h @ in_proj_w^T + b                [65536,1920]
    tgemm_bf16<0><<<dim3((3*EE)/128, BS/128, 1), 256, TG_SMEM>>>(
        h, EE, in_proj_w, EE, in_proj_b, nullptr, qkv, 3*EE, EE, 0);

    // 3) attention (tensor-core, 2 CTAs/SM) -> ctx
    attn_mma_kernel<<<BB*NH, 256, ATT_SMEM>>>(qkv, ctx);

    // 4) ao = ctx @ out_proj_w^T + b + h  (residual fused)
    tgemm_bf16<4><<<dim3(EE/128, BS/128, 1), 256, TG_SMEM>>>(
        ctx, EE, out_proj_w, EE, out_proj_b, h, ao, EE, EE, 0);

    // 5) x = LN(ao) -> x_flat (ctx buffer)
    ln_warp<false><<<BS/8, 256>>>(ao, nullptr, lnorm_g, lnorm_b, ctx, EE, BS);

    // 6) fc1 split-K=32 over 81920 aligned cols -> partials in g_h (2048 blocks)
    tgemm_bf16<3><<<dim3(HH/128, BB/128, FC1_SPLITS), 256, TG_SMEM>>>(
        ctx, KFLAT, fc1_w, LDW1, nullptr, nullptr, h, HH, FC1_KLOC, (long)BB*HH);

    // 7) reduce partials + bias + last_action tail + relu -> t1
    red_fc1<<<dim3(HH/256, BB), 256>>>(h, la, fc1_w, fc1_b, t1);

    // 8) fc2 split-K=8 -> partials in qkv; reduce: t2 = relu(.+b) + t1
    tgemm_bf16<3><<<dim3(HH/128, BB/128, 8), 256, TG_SMEM>>>(
        t1, HH, fc2_w, HH, nullptr, nullptr, qkv, HH, HH/8, (long)BB*HH);
    red_epi<8,2><<<dim3(HH/256, BB), 256>>>(qkv, (long)BB*HH, fc2_b, t1, t2, HH);

    // 9) ln1 in-place on t2
    ln_warp<false><<<BB/8, 256>>>(t2, nullptr, ln1_g, ln1_b, t2, HH, BB);

    // 10) fc3 split-K=8: t3 = relu(t2 @ fc3^T + b)  [512,1024]
    tgemm_bf16<3><<<dim3((HH/2)/128, BB/128, 8), 256, TG_SMEM>>>(
        t2, HH, fc3_w, HH, nullptr, nullptr, qkv, HH/2, HH/8, (long)BB*(HH/2));
    red_epi<8,1><<<dim3((HH/2)/256, BB), 256>>>(qkv, (long)BB*(HH/2), fc3_b, nullptr, t3, HH/2);

    // 11) fc4 split-K=8: t4 = relu(t3 @ fc4^T + b)  [512,512]
    tgemm_bf16<3><<<dim3((HH/4)/128, BB/128, 8), 256, TG_SMEM>>>(
        t3, HH/2, fc4_w, HH/2, nullptr, nullptr, qkv, HH/4, (HH/2)/8, (long)BB*(HH/4));
    red_epi<8,1><<<dim3((HH/4)/256, BB), 256>>>(qkv, (long)BB*(HH/4), fc4_b, nullptr, t4, HH/4);

    // 12) fc5 (N=129 ragged -> fp32 path)          [512,129]
    gemm_tn<64,64,16,4,4><<<dim3((AA+63)/64, BB/64), 256>>>(
        t4, HH/4, fc5_w, HH/4, fc5_b, t5, BB, AA, HH/4);

    // 13) fc6 + top-K + masked softmax -> out      [512,129]
    head_kernel<<<BB, 256>>>(t5, la, fc6_w, fc6_b, out);
}

// round 17
// speedup vs baseline: 1.0609x; 1.0609x over previous
#include <cuda_runtime.h>
#include <cstdint>
#include <math.h>

// ---------------- problem constants ----------------
#define BB   512
#define SS   128
#define EE   640
#define AA   129
#define HH   2048
#define NH   10
#define HD   64
#define KWIN 64
#define BS   (BB*SS)          // 65536
#define KFLAT (EE*SS)         // 81920
#define LDW1 (KFLAT + AA)     // 82049
#define FC1_SPLITS 32
#define FC1_KLOC   (KFLAT/FC1_SPLITS)   // 2560

// ---------------- scratch (device globals, no allocs) ----------------
__device__ float g_h[BS * EE];          // h; later fc1 split-K partials
__device__ float g_qkv[BS * 3 * EE];    // qkv; later fc2/3/4 partials
__device__ float g_ctx[BS * EE];        // ctx; x_flat
__device__ float g_ao[BS * EE];         // attn_out (+h fused)
__device__ float g_t1[BB * HH];
__device__ float g_t2[BB * HH];
__device__ float g_t3[BB * (HH/2)];
__device__ float g_t4[BB * (HH/4)];
__device__ float g_t5[BB * AA];

// ================= helpers =================
#define MMA_BF16(c, a, b) \
    asm volatile("mma.sync.aligned.m16n8k16.row.col.f32.bf16.bf16.f32 " \
        "{%0,%1,%2,%3}, {%4,%5,%6,%7}, {%8,%9}, {%0,%1,%2,%3};" \
        : "+f"((c)[0]), "+f"((c)[1]), "+f"((c)[2]), "+f"((c)[3]) \
        : "r"((a)[0]), "r"((a)[1]), "r"((a)[2]), "r"((a)[3]), \
          "r"((b)[0]), "r"((b)[1]))
#define LDSM4(r0, r1, r2, r3, addr) \
    asm volatile("ldmatrix.sync.aligned.m8n8.x4.shared.b16 {%0,%1,%2,%3}, [%4];" \
        : "=r"(r0), "=r"(r1), "=r"(r2), "=r"(r3) : "r"(addr))

__device__ __forceinline__ uint32_t smem_u32(const void* p) {
    uint32_t a;
    asm("{ .reg .u64 t; cvta.to.shared.u64 t, %1; cvt.u32.u64 %0, t; }" : "=r"(a) : "l"(p));
    return a;
}

// split fp32x4 -> bf16x2 (hi,lo) pairs and store to smem (2 u32 words each)
__device__ __forceinline__ void splitStoreBf(float4 f, uint32_t* hi, uint32_t* lo, int off) {
    uint32_t h01, h23;
    asm("cvt.rn.bf16x2.f32 %0, %1, %2;" : "=r"(h01) : "f"(f.y), "f"(f.x));
    asm("cvt.rn.bf16x2.f32 %0, %1, %2;" : "=r"(h23) : "f"(f.w), "f"(f.z));
    float hx = __uint_as_float(h01 << 16);
    float hy = __uint_as_float(h01 & 0xFFFF0000u);
    float hz = __uint_as_float(h23 << 16);
    float hw = __uint_as_float(h23 & 0xFFFF0000u);
    uint32_t l01, l23;
    asm("cvt.rn.bf16x2.f32 %0, %1, %2;" : "=r"(l01) : "f"(f.y - hy), "f"(f.x - hx));
    asm("cvt.rn.bf16x2.f32 %0, %1, %2;" : "=r"(l23) : "f"(f.w - hw), "f"(f.z - hz));
    hi[off] = h01; hi[off + 1] = h23;
    lo[off] = l01; lo[off + 1] = l23;
}
// split two scalars into one bf16x2 hi word + lo word
__device__ __forceinline__ void splitPairBf(float v0, float v1, uint32_t& hp, uint32_t& lp) {
    asm("cvt.rn.bf16x2.f32 %0, %1, %2;" : "=r"(hp) : "f"(v1), "f"(v0));
    float h0 = __uint_as_float(hp << 16);
    float h1 = __uint_as_float(hp & 0xFFFF0000u);
    asm("cvt.rn.bf16x2.f32 %0, %1, %2;" : "=r"(lp) : "f"(v1 - h1), "f"(v0 - h0));
}

// ============== 3xBF16 mma.sync GEMM:  C = A(M,K) @ W(N,K)^T ==============
// EPI: 0 bias | 3 raw partial (split-K) | 4 bias + Res add (no relu).
// Block tile 128x128, BK=32, 256 threads, warp grid 2x4, warp tile 64x32.
// Fragment loads via ldmatrix.x4 (conflict-free with row stride 20 u32).
#define RS32 20
#define A_U32 (128*RS32)
#define W_U32 (128*RS32)
#define BUF_U32 (2*A_U32 + 2*W_U32)
#define TG_SMEM (2*BUF_U32*4)             // 81920 B
template<int EPI>
__global__ void __launch_bounds__(256, 2)
tgemm_bf16(const float* __restrict__ A, long lda,
           const float* __restrict__ W, long ldw,
           const float* __restrict__ bias, const float* __restrict__ Res,
           float* __restrict__ C, long ldc, int Kloc, long partStride)
{
    extern __shared__ uint32_t smu[];

    const int tid = threadIdx.x;
    const int wid = tid >> 5;
    const int lane = tid & 31;
    const int g   = lane >> 2;
    const int tig = lane & 3;
    const int wm = (wid & 1) * 64;
    const int wn = (wid >> 1) * 32;

    const int m0 = blockIdx.y * 128;
    const int n0 = blockIdx.x * 128;
    const long kbase = (long)blockIdx.z * Kloc;
    float* Cp = C + (EPI == 3 ? (long)blockIdx.z * partStride : 0);
    const bool wal = ((ldw & 3) == 0);
    const int KT = Kloc / 32;

    const uint32_t sbase = smem_u32(smu);
    // ldmatrix per-lane offsets (u32 units)
    const int aoff = (lane & 15) * RS32 + (lane >> 4) * 4;               // A x4
    const int sub  = lane >> 3;
    const int boff = ((lane & 7) + (sub >> 1) * 8) * RS32 + (sub & 1) * 4; // B x4 (2 nt)

    float acc[4][4][4];
#pragma unroll
    for (int mt = 0; mt < 4; mt++)
#pragma unroll
        for (int nt = 0; nt < 4; nt++)
#pragma unroll
            for (int r = 0; r < 4; r++) acc[mt][nt][r] = 0.f;

    float4 fa[4], fw[4];

    auto loadFrag = [&](int kt) {
        const long kk = kbase + (long)kt * 32;
#pragma unroll
        for (int i = 0; i < 4; i++) {
            int c = tid + i * 256; int row = c >> 3, q = c & 7;
            fa[i] = *reinterpret_cast<const float4*>(A + (size_t)(m0 + row) * lda + kk + q * 4);
            const float* pw = W + (size_t)(n0 + row) * ldw + kk + q * 4;
            if (wal) fw[i] = *reinterpret_cast<const float4*>(pw);
            else     fw[i] = make_float4(pw[0], pw[1], pw[2], pw[3]);
        }
    };
    auto storeFrag = [&](int sbi) {
        uint32_t* Ah = smu + sbi * BUF_U32;
        uint32_t* Al = Ah + A_U32;
        uint32_t* Wh = Al + A_U32;
        uint32_t* Wl = Wh + W_U32;
#pragma unroll
        for (int i = 0; i < 4; i++) {
            int c = tid + i * 256; int row = c >> 3, q = c & 7;
            splitStoreBf(fa[i], Ah, Al, row * RS32 + q * 2);
            splitStoreBf(fw[i], Wh, Wl, row * RS32 + q * 2);
        }
    };
    auto compute = [&](int sbi) {
        const uint32_t bA  = sbase + (sbi * BUF_U32) * 4;
        const uint32_t bAl = bA + A_U32 * 4;
        const uint32_t bW  = bAl + A_U32 * 4;
        const uint32_t bWl = bW + W_U32 * 4;
#pragma unroll
        for (int ks = 0; ks < 2; ks++) {
            const int kw = ks * 8;
            uint32_t bh[4][2], bl[4][2];
#pragma unroll
            for (int p = 0; p < 2; p++) {
                const uint32_t off = ((wn + p * 16) * RS32 + kw + boff) * 4;
                LDSM4(bh[2*p][0], bh[2*p][1], bh[2*p+1][0], bh[2*p+1][1], bW  + off);
                LDSM4(bl[2*p][0], bl[2*p][1], bl[2*p+1][0], bl[2*p+1][1], bWl + off);
            }
#pragma unroll
            for (int mt = 0; mt < 4; mt++) {
                const uint32_t off = ((wm + mt * 16) * RS32 + kw + aoff) * 4;
                uint32_t ah[4], al[4];
                LDSM4(ah[0], ah[1], ah[2], ah[3], bA  + off);
                LDSM4(al[0], al[1], al[2], al[3], bAl + off);
#pragma unroll
                for (int nt = 0; nt < 4; nt++) {
                    MMA_BF16(acc[mt][nt], al, bh[nt]);
                    MMA_BF16(acc[mt][nt], ah, bl[nt]);
                    MMA_BF16(acc[mt][nt], ah, bh[nt]);
                }
            }
        }
    };

    loadFrag(0);
    storeFrag(0);
    if (KT > 1) loadFrag(1);
    __syncthreads();

    for (int kt = 0; kt < KT; kt++) {
        if (kt + 1 < KT) storeFrag((kt + 1) & 1);
        if (kt + 2 < KT) loadFrag(kt + 2);
        compute(kt & 1);
        __syncthreads();
    }

#pragma unroll
    for (int mt = 0; mt < 4; mt++) {
#pragma unroll
        for (int nt = 0; nt < 4; nt++) {
            const int col = n0 + wn + nt * 8 + 2 * tig;
            float2 b2 = make_float2(0.f, 0.f);
            if (EPI != 3) b2 = *reinterpret_cast<const float2*>(bias + col);
#pragma unroll
            for (int half = 0; half < 2; half++) {
                const int row = m0 + wm + mt * 16 + g + half * 8;
                float vx = acc[mt][nt][2*half + 0] + b2.x;
                float vy = acc[mt][nt][2*half + 1] + b2.y;
                if (EPI == 4) {
                    float2 r2 = *reinterpret_cast<const float2*>(Res + (size_t)row * ldc + col);
                    vx += r2.x; vy += r2.y;
                }
                *reinterpret_cast<float2*>(Cp + (size_t)row * ldc + col) = make_float2(vx, vy);
            }
        }
    }
}

// ============== generic split-K reduce: bias [+relu] [+res] ==============
template<int NSPLIT, int EPI>
__global__ void red_epi(const float* __restrict__ part, long stride,
                        const float* __restrict__ bias, const float* __restrict__ Res,
                        float* __restrict__ out, int N)
{
    const int m = blockIdx.y;
    const int n = blockIdx.x * 256 + threadIdx.x;
    float s = bias[n];
#pragma unroll
    for (int z = 0; z < NSPLIT; z++)
        s += part[(size_t)z * stride + (size_t)m * N + n];
    s = fmaxf(s, 0.f);
    if (EPI == 2) s += Res[(size_t)m * N + n];
    out[(size_t)m * N + n] = s;
}

// ============== fc1 split-K reduce + bias + last_action tail + relu ==============
__global__ void red_fc1(const float* __restrict__ part, const float* __restrict__ la,
                        const float* __restrict__ w1, const float* __restrict__ b1,
                        float* __restrict__ t1)
{
    const int m = blockIdx.y;
    const int n = blockIdx.x * 256 + threadIdx.x;
    __shared__ float las[AA];
    if (threadIdx.x < AA) las[threadIdx.x] = la[m * AA + threadIdx.x];
    __syncthreads();
    float s = b1[n];
#pragma unroll
    for (int z = 0; z < FC1_SPLITS; z++)
        s += part[(size_t)z * (BB * HH) + (size_t)m * HH + n];
    const float* w = w1 + (size_t)n * LDW1 + KFLAT;
    float acc = 0.f;
    for (int j = 0; j < AA; j++) acc += las[j] * w[j];
    t1[(size_t)m * HH + n] = fmaxf(s + acc, 0.f);
}

// ================= fp32 fallback GEMM (fc5 only, N=129 ragged) =================
template<int BM, int BN, int BK, int TM, int TN>
__global__ void __launch_bounds__((BM/TM)*(BN/TN))
gemm_tn(const float* __restrict__ A, int lda,
        const float* __restrict__ W, int ldw,
        const float* __restrict__ bias,
        float* __restrict__ C, int M, int N, int K)
{
    constexpr int THREADS = (BM/TM)*(BN/TN);
    constexpr int KV = BK / 4;
    __shared__ __align__(16) float As[BK][BM];
    __shared__ __align__(16) float Ws[BK][BN];
    const int tid = threadIdx.x;
    const int m0 = blockIdx.y * BM;
    const int n0 = blockIdx.x * BN;
    const int tnx = tid % (BN/TN);
    const int tmy = tid / (BN/TN);
    float acc[TM][TN];
#pragma unroll
    for (int i = 0; i < TM; i++)
#pragma unroll
        for (int j = 0; j < TN; j++) acc[i][j] = 0.f;
    for (int k0 = 0; k0 < K; k0 += BK) {
#pragma unroll
        for (int it = 0; it < (BM*KV)/THREADS; it++) {
            int v = tid + it * THREADS; int row = v / KV, kq = v % KV;
            float4 f = make_float4(0.f,0.f,0.f,0.f);
            if (m0 + row < M) f = *reinterpret_cast<const float4*>(A + (size_t)(m0+row)*lda + k0 + kq*4);
            As[kq*4+0][row]=f.x; As[kq*4+1][row]=f.y; As[kq*4+2][row]=f.z; As[kq*4+3][row]=f.w;
        }
#pragma unroll
        for (int it = 0; it < (BN*KV)/THREADS; it++) {
            int v = tid + it * THREADS; int row = v / KV, kq = v % KV;
            float4 f = make_float4(0.f,0.f,0.f,0.f);
            if (n0 + row < N) f = *reinterpret_cast<const float4*>(W + (size_t)(n0+row)*ldw + k0 + kq*4);
            Ws[kq*4+0][row]=f.x; Ws[kq*4+1][row]=f.y; Ws[kq*4+2][row]=f.z; Ws[kq*4+3][row]=f.w;
        }
        __syncthreads();
#pragma unroll
        for (int kk = 0; kk < BK; kk++) {
            float a[TM], w[TN];
#pragma unroll
            for (int i = 0; i < TM; i++) a[i] = As[kk][tmy*TM + i];
#pragma unroll
            for (int j = 0; j < TN; j++) w[j] = Ws[kk][tnx*TN + j];
#pragma unroll
            for (int i = 0; i < TM; i++)
#pragma unroll
                for (int j = 0; j < TN; j++) acc[i][j] += a[i] * w[j];
        }
        __syncthreads();
    }
#pragma unroll
    for (int i = 0; i < TM; i++) {
        int m = m0 + tmy*TM + i; if (m >= M) continue;
#pragma unroll
        for (int j = 0; j < TN; j++) {
            int n = n0 + tnx*TN + j; if (n >= N) continue;
            C[(size_t)m * N + n] = acc[i][j] + bias[n];
        }
    }
}

// ================= attention via 3xBF16 MMA, register softmax, 2 CTAs/SM =================
#define ATT_RS  36
#define ATT_PRS 68
#define ATT_VRS 68
#define ATT_SMEM (28160*4)    // 112640 B
__global__ void __launch_bounds__(256, 2)
attn_mma_kernel(const float* __restrict__ qkv, float* __restrict__ ctx)
{
    extern __shared__ uint32_t su[];
    uint32_t* Qh = su;
    uint32_t* Ql = su + 4608;
    uint32_t* Kh = su + 9216;
    uint32_t* Kl = su + 13824;
    float*    Vst = reinterpret_cast<float*>(su + 18432);   // [128][68]
    uint32_t* Vth = su;                                      // after S-MMA
    uint32_t* Vtl = su + 4352;
    uint32_t* Ph  = su + 9216;                               // [128][68]
    uint32_t* Pl  = su + 17920;
    float*    scrM = reinterpret_cast<float*>(su + 27136);   // [128][4]
    float*    scrS = reinterpret_cast<float*>(su + 27648);   // [128][4]

    const int b = blockIdx.x / NH;
    const int h = blockIdx.x % NH;
    const int tid = threadIdx.x;
    const int wid = tid >> 5;
    const int lane = tid & 31;
    const int g   = lane >> 2;
    const int tig = lane & 3;
    const int wm  = (wid & 1) * 64;
    const int wn  = (wid >> 1) * 32;
    const int wnIdx = wid >> 1;
    const size_t base = (size_t)b * SS * (3*EE) + (size_t)h * HD;

    // phase 1: Q (scaled) & K -> hi/lo planes; V -> fp32 staging
#pragma unroll
    for (int i = 0; i < 8; i++) {
        int c = tid + i * 256;
        int row = c >> 4, q4 = c & 15;
        const float* p = qkv + base + (size_t)row * (3*EE);
        float4 fq = *reinterpret_cast<const float4*>(p + q4*4);
        fq.x *= 0.125f; fq.y *= 0.125f; fq.z *= 0.125f; fq.w *= 0.125f;
        splitStoreBf(fq, Qh, Ql, row*ATT_RS + q4*2);
        float4 fk = *reinterpret_cast<const float4*>(p + EE + q4*4);
        splitStoreBf(fk, Kh, Kl, row*ATT_RS + q4*2);
        float4 fv = *reinterpret_cast<const float4*>(p + 2*EE + q4*4);
        *reinterpret_cast<float4*>(Vst + row*68 + q4*4) = fv;
    }
    __syncthreads();

    // phase 2: S = Q @ K^T, accs stay in registers
    float acc[4][4][4];
#pragma unroll
    for (int mt = 0; mt < 4; mt++)
#pragma unroll
        for (int nt = 0; nt < 4; nt++)
#pragma unroll
            for (int r = 0; r < 4; r++) acc[mt][nt][r] = 0.f;

#pragma unroll
    for (int c = 0; c < 4; c++) {
        const int kb = c * 8;
        uint32_t bh[4][2], bl[4][2];
#pragma unroll
        for (int nt = 0; nt < 4; nt++) {
            const int r = (wn + nt*8 + g)*ATT_RS + kb + tig;
            bh[nt][0] = Kh[r]; bh[nt][1] = Kh[r + 4];
            bl[nt][0] = Kl[r]; bl[nt][1] = Kl[r + 4];
        }
#pragma unroll
        for (int mt = 0; mt < 4; mt++) {
            const int r = (wm + mt*16 + g)*ATT_RS + kb + tig;
            uint32_t ah[4], al[4];
            ah[0] = Qh[r]; ah[1] = Qh[r + 8*ATT_RS];
            ah[2] = Qh[r + 4]; ah[3] = Qh[r + 8*ATT_RS + 4];
            al[0] = Ql[r]; al[1] = Ql[r + 8*ATT_RS];
            al[2] = Ql[r + 4]; al[3] = Ql[r + 8*ATT_RS + 4];
#pragma unroll
            for (int nt = 0; nt < 4; nt++) {
                MMA_BF16(acc[mt][nt], al, bh[nt]);
                MMA_BF16(acc[mt][nt], ah, bl[nt]);
                MMA_BF16(acc[mt][nt], ah, bh[nt]);
            }
        }
    }
    __syncthreads();   // Q/K reads done; safe to overwrite Q area

    // phase 3: transpose V -> planes (Q area)  +  write per-warp row maxes
#pragma unroll
    for (int i = 0; i < 16; i++) {
        int o = tid + i * 256;
        int d = o >> 6, kc = o & 63;
        float v0 = Vst[(2*kc    )*68 + d];
        float v1 = Vst[(2*kc + 1)*68 + d];
        uint32_t hp, lp;
        splitPairBf(v0, v1, hp, lp);
        Vth[d*ATT_VRS + kc] = hp;
        Vtl[d*ATT_VRS + kc] = lp;
    }
#pragma unroll
    for (int mt = 0; mt < 4; mt++)
#pragma unroll
        for (int half = 0; half < 2; half++) {
            float m = -1e30f;
#pragma unroll
            for (int nt = 0; nt < 4; nt++) {
                m = fmaxf(m, acc[mt][nt][2*half]);
                m = fmaxf(m, acc[mt][nt][2*half + 1]);
            }
            m = fmaxf(m, __shfl_xor_sync(0xffffffffu, m, 1));
            m = fmaxf(m, __shfl_xor_sync(0xffffffffu, m, 2));
            if (tig == 0) scrM[(wm + mt*16 + g + half*8)*4 + wnIdx] = m;
        }
    __syncthreads();

    // phase 4a: exp + per-warp sums
#pragma unroll
    for (int mt = 0; mt < 4; mt++)
#pragma unroll
        for (int half = 0; half < 2; half++) {
            const int row = wm + mt*16 + g + half*8;
            float mx = fmaxf(fmaxf(scrM[row*4], scrM[row*4+1]),
                             fmaxf(scrM[row*4+2], scrM[row*4+3]));
            float s = 0.f;
#pragma unroll
            for (int nt = 0; nt < 4; nt++) {
                float e0 = expf(acc[mt][nt][2*half]     - mx);
                float e1 = expf(acc[mt][nt][2*half + 1] - mx);
                acc[mt][nt][2*half]     = e0;
                acc[mt][nt][2*half + 1] = e1;
                s += e0 + e1;
            }
            s += __shfl_xor_sync(0xffffffffu, s, 1);
            s += __shfl_xor_sync(0xffffffffu, s, 2);
            if (tig == 0) scrS[row*4 + wnIdx] = s;
        }
    __syncthreads();

    // phase 4b: normalize + write P planes (K + Vst area, both dead)
#pragma unroll
    for (int mt = 0; mt < 4; mt++)
#pragma unroll
        for (int half = 0; half < 2; half++) {
            const int row = wm + mt*16 + g + half*8;
            float tot = scrS[row*4] + scrS[row*4+1] + scrS[row*4+2] + scrS[row*4+3];
            float inv = 1.f / tot;
#pragma unroll
            for (int nt = 0; nt < 4; nt++) {
                float p0 = acc[mt][nt][2*half]     * inv;
                float p1 = acc[mt][nt][2*half + 1] * inv;
                uint32_t hp, lp;
                splitPairBf(p0, p1, hp, lp);
                const int cw = (wn >> 1) + nt*4 + tig;
                Ph[row*ATT_PRS + cw] = hp;
                Pl[row*ATT_PRS + cw] = lp;
            }
        }
    __syncthreads();

    // phase 5: ctx = P @ V  (128x64x128), warp tile 64x16
    {
        const int wn2 = (wid >> 1) * 16;
        float acc2[4][2][4];
#pragma unroll
        for (int mt = 0; mt < 4; mt++)
#pragma unroll
            for (int nt = 0; nt < 2; nt++)
#pragma unroll
                for (int r = 0; r < 4; r++) acc2[mt][nt][r] = 0.f;

#pragma unroll
        for (int c = 0; c < 8; c++) {
            const int kb = c * 8;
            uint32_t bh[2][2], bl[2][2];
#pragma unroll
            for (int nt = 0; nt < 2; nt++) {
                const int r = (wn2 + nt*8 + g)*ATT_VRS + kb + tig;
                bh[nt][0] = Vth[r]; bh[nt][1] = Vth[r + 4];
                bl[nt][0] = Vtl[r]; bl[nt][1] = Vtl[r + 4];
            }
#pragma unroll
            for (int mt = 0; mt < 4; mt++) {
                const int r = (wm + mt*16 + g)*ATT_PRS + kb + tig;
                uint32_t ah[4], al[4];
                ah[0] = Ph[r]; ah[1] = Ph[r + 8*ATT_PRS];
                ah[2] = Ph[r + 4]; ah[3] = Ph[r + 8*ATT_PRS + 4];
                al[0] = Pl[r]; al[1] = Pl[r + 8*ATT_PRS];
                al[2] = Pl[r + 4]; al[3] = Pl[r + 8*ATT_PRS + 4];
#pragma unroll
                for (int nt = 0; nt < 2; nt++) {
                    MMA_BF16(acc2[mt][nt], al, bh[nt]);
                    MMA_BF16(acc2[mt][nt], ah, bl[nt]);
                    MMA_BF16(acc2[mt][nt], ah, bh[nt]);
                }
            }
        }
#pragma unroll
        for (int mt = 0; mt < 4; mt++)
#pragma unroll
            for (int nt = 0; nt < 2; nt++) {
                const int col = wn2 + nt*8 + 2*tig;
#pragma unroll
                for (int half = 0; half < 2; half++) {
                    const int row = wm + mt*16 + g + half*8;
                    *reinterpret_cast<float2*>(ctx + ((size_t)b*SS + row)*EE + h*HD + col) =
                        make_float2(acc2[mt][nt][2*half], acc2[mt][nt][2*half + 1]);
                }
            }
    }
}

// ================= layernorm: warp per row =================
template<bool ADD>
__global__ void ln_warp(const float* __restrict__ X, const float* __restrict__ Y,
                        const float* __restrict__ g, const float* __restrict__ be,
                        float* __restrict__ out, int D, int rows)
{
    const int w = (blockIdx.x * blockDim.x + threadIdx.x) >> 5;
    if (w >= rows) return;
    const int lane = threadIdx.x & 31;
    const float* x = X + (size_t)w * D;
    const float* y = ADD ? (Y + (size_t)w * D) : nullptr;
    float s = 0.f, s2 = 0.f;
    for (int c = lane * 4; c < D; c += 128) {
        float4 v = *reinterpret_cast<const float4*>(x + c);
        if (ADD) {
            float4 u = *reinterpret_cast<const float4*>(y + c);
            v.x += u.x; v.y += u.y; v.z += u.z; v.w += u.w;
        }
        s  += (v.x + v.y) + (v.z + v.w);
        s2 += (v.x*v.x + v.y*v.y) + (v.z*v.z + v.w*v.w);
    }
#pragma unroll
    for (int o = 16; o > 0; o >>= 1) {
        s  += __shfl_xor_sync(0xffffffffu, s,  o);
        s2 += __shfl_xor_sync(0xffffffffu, s2, o);
    }
    float mean = s / (float)D;
    float var  = s2 / (float)D - mean * mean;
    float inv  = rsqrtf(var + 1e-5f);
    for (int c = lane * 4; c < D; c += 128) {
        float4 v = *reinterpret_cast<const float4*>(x + c);
        if (ADD) {
            float4 u = *reinterpret_cast<const float4*>(y + c);
            v.x += u.x; v.y += u.y; v.z += u.z; v.w += u.w;
        }
        float4 gg = *reinterpret_cast<const float4*>(g + c);
        float4 bb = *reinterpret_cast<const float4*>(be + c);
        v.x = (v.x - mean) * inv * gg.x + bb.x;
        v.y = (v.y - mean) * inv * gg.y + bb.y;
        v.z = (v.z - mean) * inv * gg.z + bb.z;
        v.w = (v.w - mean) * inv * gg.w + bb.w;
        *reinterpret_cast<float4*>(out + (size_t)w * D + c) = v;
    }
}

// ================= fc6 + top-K + masked softmax =================
__global__ void head_kernel(const float* __restrict__ t5, const float* __restrict__ la,
                            const float* __restrict__ w6, const float* __restrict__ b6,
                            float* __restrict__ out)
{
    const int b = blockIdx.x;
    __shared__ float cat[2*AA];
    __shared__ float sc[AA];
    __shared__ float red[256];
    const int tid = threadIdx.x;

    for (int i = tid; i < 2*AA; i += 256)
        cat[i] = (i < AA) ? t5[b*AA + i] : la[b*AA + (i - AA)];
    __syncthreads();

    if (tid < AA) {
        float a = b6[tid];
        const float* w = w6 + tid * (2*AA);
        for (int j = 0; j < 2*AA; j++) a += w[j] * cat[j];
        sc[tid] = a;
    }
    __syncthreads();

    bool winner = false; float v = 0.f;
    if (tid < AA) {
        v = sc[tid];
        int cnt = 0;
        for (int j = 0; j < AA; j++) {
            float u = sc[j];
            cnt += (u > v) || (u == v && j < tid);
        }
        winner = cnt < KWIN;
    }
    red[tid] = (tid < AA && winner) ? v : -1e30f;
    __syncthreads();
    for (int s = 128; s > 0; s >>= 1) {
        if (tid < s) red[tid] = fmaxf(red[tid], red[tid + s]);
        __syncthreads();
    }
    float mx = red[0];
    __syncthreads();
    float e = (tid < AA && winner) ? expf(v - mx) : 0.f;
    red[tid] = e;
    __syncthreads();
    for (int s = 128; s > 0; s >>= 1) {
        if (tid < s) red[tid] += red[tid + s];
        __syncthreads();
    }
    float inv = 1.f / red[0];
    if (tid < AA) out[b*AA + tid] = e * inv;
}

// ================= launcher =================
extern "C" void kernel_launch(void* const* d_in, const int* in_sizes, int n_in,
                              void* d_out, int out_size)
{
    const float* hist      = (const float*)d_in[0];
    const float* la        = (const float*)d_in[1];
    const float* embed_w   = (const float*)d_in[2];
    const float* embed_b   = (const float*)d_in[3];
    const float* in_proj_w = (const float*)d_in[4];
    const float* in_proj_b = (const float*)d_in[5];
    const float* out_proj_w= (const float*)d_in[6];
    const float* out_proj_b= (const float*)d_in[7];
    const float* lnorm_g   = (const float*)d_in[8];
    const float* lnorm_b   = (const float*)d_in[9];
    const float* fc1_w     = (const float*)d_in[10];
    const float* fc1_b     = (const float*)d_in[11];
    const float* fc2_w     = (const float*)d_in[12];
    const float* fc2_b     = (const float*)d_in[13];
    const float* ln1_g     = (const float*)d_in[14];
    const float* ln1_b     = (const float*)d_in[15];
    const float* fc3_w     = (const float*)d_in[16];
    const float* fc3_b     = (const float*)d_in[17];
    const float* fc4_w     = (const float*)d_in[18];
    const float* fc4_b     = (const float*)d_in[19];
    const float* fc5_w     = (const float*)d_in[20];
    const float* fc5_b     = (const float*)d_in[21];
    const float* fc6_w     = (const float*)d_in[22];
    const float* fc6_b     = (const float*)d_in[23];
    float* out = (float*)d_out;

    float *h, *qkv, *ctx, *ao, *t1, *t2, *t3, *t4, *t5;
    cudaGetSymbolAddress((void**)&h,   g_h);
    cudaGetSymbolAddress((void**)&qkv, g_qkv);
    cudaGetSymbolAddress((void**)&ctx, g_ctx);
    cudaGetSymbolAddress((void**)&ao,  g_ao);
    cudaGetSymbolAddress((void**)&t1,  g_t1);
    cudaGetSymbolAddress((void**)&t2,  g_t2);
    cudaGetSymbolAddress((void**)&t3,  g_t3);
    cudaGetSymbolAddress((void**)&t4,  g_t4);
    cudaGetSymbolAddress((void**)&t5,  g_t5);

    cudaFuncSetAttribute(tgemm_bf16<0>, cudaFuncAttributeMaxDynamicSharedMemorySize, TG_SMEM);
    cudaFuncSetAttribute(tgemm_bf16<3>, cudaFuncAttributeMaxDynamicSharedMemorySize, TG_SMEM);
    cudaFuncSetAttribute(tgemm_bf16<4>, cudaFuncAttributeMaxDynamicSharedMemorySize, TG_SMEM);
    cudaFuncSetAttribute(attn_mma_kernel, cudaFuncAttributeMaxDynamicSharedMemorySize, ATT_SMEM);

    // 1) embed: h = hist @ embed_w^T + b          [65536,640]
    tgemm_bf16<0><<<dim3(EE/128, BS/128, 1), 256, TG_SMEM>>>(
        hist, EE, embed_w, EE, embed_b, nullptr, h, EE, EE, 0);

    // 2) qkv = h @ in_proj_w^T + b                [65536,1920]
    tgemm_bf16<0><<<dim3((3*EE)/128, BS/128, 1), 256, TG_SMEM>>>(
        h, EE, in_proj_w, EE, in_proj_b, nullptr, qkv, 3*EE, EE, 0);

    // 3) attention (tensor-core, 2 CTAs/SM) -> ctx
    attn_mma_kernel<<<BB*NH, 256, ATT_SMEM>>>(qkv, ctx);

    // 4) ao = ctx @ out_proj_w^T + b + h  (residual fused)
    tgemm_bf16<4><<<dim3(EE/128, BS/128, 1), 256, TG_SMEM>>>(
        ctx, EE, out_proj_w, EE, out_proj_b, h, ao, EE, EE, 0);

    // 5) x = LN(ao) -> x_flat (ctx buffer)
    ln_warp<false><<<BS/8, 256>>>(ao, nullptr, lnorm_g, lnorm_b, ctx, EE, BS);

    // 6) fc1 split-K=32 over 81920 aligned cols -> partials in g_h (2048 blocks)
    tgemm_bf16<3><<<dim3(HH/128, BB/128, FC1_SPLITS), 256, TG_SMEM>>>(
        ctx, KFLAT, fc1_w, LDW1, nullptr, nullptr, h, HH, FC1_KLOC, (long)BB*HH);

    // 7) reduce partials + bias + last_action tail + relu -> t1
    red_fc1<<<dim3(HH/256, BB), 256>>>(h, la, fc1_w, fc1_b, t1);

    // 8) fc2 split-K=8 -> partials in qkv; reduce: t2 = relu(.+b) + t1
    tgemm_bf16<3><<<dim3(HH/128, BB/128, 8), 256, TG_SMEM>>>(
        t1, HH, fc2_w, HH, nullptr, nullptr, qkv, HH, HH/8, (long)BB*HH);
    red_epi<8,2><<<dim3(HH/256, BB), 256>>>(qkv, (long)BB*HH, fc2_b, t1, t2, HH);

    // 9) ln1 in-place on t2
    ln_warp<false><<<BB/8, 256>>>(t2, nullptr, ln1_g, ln1_b, t2, HH, BB);

    // 10) fc3 split-K=8: t3 = relu(t2 @ fc3^T + b)  [512,1024]
    tgemm_bf16<3><<<dim3((HH/2)/128, BB/128, 8), 256, TG_SMEM>>>(
        t2, HH, fc3_w, HH, nullptr, nullptr, qkv, HH/2, HH/8, (long)BB*(HH/2));
    red_epi<8,1><<<dim3((HH/2)/256, BB), 256>>>(qkv, (long)BB*(HH/2), fc3_b, nullptr, t3, HH/2);

    // 11) fc4 split-K=8: t4 = relu(t3 @ fc4^T + b)  [512,512]
    tgemm_bf16<3><<<dim3((HH/4)/128, BB/128, 8), 256, TG_SMEM>>>(
        t3, HH/2, fc4_w, HH/2, nullptr, nullptr, qkv, HH/4, (HH/2)/8, (long)BB*(HH/4));
    red_epi<8,1><<<dim3((HH/4)/256, BB), 256>>>(qkv, (long)BB*(HH/4), fc4_b, nullptr, t4, HH/4);

    // 12) fc5 (N=129 ragged -> fp32 path)          [512,129]
    gemm_tn<64,64,16,4,4><<<dim3((AA+63)/64, BB/64), 256>>>(
        t4, HH/4, fc5_w, HH/4, fc5_b, t5, BB, AA, HH/4);

    // 13) fc6 + top-K + masked softmax -> out      [512,129]
    head_kernel<<<BB, 256>>>(t5, la, fc6_w, fc6_b, out);
}